// round 12
// baseline (speedup 1.0000x reference)
#include <cuda_runtime.h>
#include <cuda_bf16.h>
#include <cstddef>

// Problem constants (fixed shapes per reference)
constexpr int B_ = 16;
constexpr int C_ = 256;
constexpr int L_ = 8192;
constexpr int D_ = 512;   // d_inner
constexpr int A_ = 64;    // att_dim

constexpr int PREP_BLOCKS = 32;   // blocks that also compute u
constexpr int GRID_MAIN   = B_ * (L_ / 16);   // 8192

// u[d] = w_out @ wv, published by blocks 0..31; flag counters (zero-init,
// reset by the last finishing block each run for graph-replay determinism).
__device__ float g_u[D_];
__device__ int   g_prep_done;
__device__ int   g_main_done;

// Single launch. Every block processes one (b, 16-l) tile in the proven R8
// structure (60us, measured x4). Blocks 0..31 first compute u (coalesced:
// 32 blk x 256 thr x one float4 chunk of w_out), fence, and bump a counter.
// Main blocks only need u at the EPILOGUE, so the publish latency (~2us,
// wave-1 guaranteed) hides under the DRAM-bound compute phase (>=5us).
__global__ void __launch_bounds__(256, 6)
fused_kernel(const float* __restrict__ h_v,
             const float* __restrict__ wq,
             const float* __restrict__ wk,
             const float* __restrict__ wv,
             const float* __restrict__ w_out,
             float* __restrict__ out) {
    __shared__ float s_u[D_];
    __shared__ float s_red[256];
    __shared__ float s_red2[256];
    __shared__ float s_sval[16];
    __shared__ __align__(16) float s_pooled[16];

    const int tid = threadIdx.x;
    const int ll  = tid & 15;   // l within tile
    const int cg  = tid >> 4;   // c-group 0..15 (16 c each)

    const int bidx   = blockIdx.x;          // 8192 blocks, tile == bidx
    const int b      = bidx >> 9;
    const int l_base = (bidx & 511) << 4;

    // ---- blocks 0..31: compute and publish u ----
    if (bidx < PREP_BLOCKS) {
        const int idx = bidx * 256 + tid;   // 0..8191 float4 chunks of w_out
        const int q   = idx & 15;
        const int row = idx >> 4;
        const float4 vv = reinterpret_cast<const float4*>(wv)[q];
        const float4 r  = reinterpret_cast<const float4*>(w_out)[idx];
        float acc = r.x * vv.x + r.y * vv.y + r.z * vv.z + r.w * vv.w;
        acc += __shfl_xor_sync(0xffffffffu, acc, 8);
        acc += __shfl_xor_sync(0xffffffffu, acc, 4);
        acc += __shfl_xor_sync(0xffffffffu, acc, 2);
        acc += __shfl_xor_sync(0xffffffffu, acc, 1);
        if (q == 0) g_u[row] = acc;
        __threadfence();
        __syncthreads();
        if (tid == 0) atomicAdd(&g_prep_done, 1);
    }

    // ---- per-block coef = <wq,wk>/8 (warp 0 only; consumers are tid<16) ----
    float coef = 0.f;
    if (tid < 32) {
        float pqk = wq[tid] * wk[tid] + wq[tid + 32] * wk[tid + 32];
#pragma unroll
        for (int m = 16; m >= 1; m >>= 1)
            pqk += __shfl_xor_sync(0xffffffffu, pqk, m);
        coef = pqk * 0.125f;  // 1/sqrt(64)
    }

    // ---- single read of h_v: 16 values per thread (imm-offset LDGs) ----
    const float* p = h_v + ((size_t)b * C_ + (size_t)cg * 16) * L_ + l_base + ll;
    float h[16];
#pragma unroll
    for (int i = 0; i < 16; i++) h[i] = __ldcs(p + (size_t)i * L_);

    // ---- mean over C ----
    float sum = 0.f;
#pragma unroll
    for (int i = 0; i < 16; i++) sum += h[i];
    s_red[tid] = sum;
    __syncthreads();
    if (tid < 16) {
        float t = 0.f;
#pragma unroll
        for (int j = 0; j < 16; j++) t += s_red[tid + 16 * j];
        s_sval[tid] = t * ((1.0f / 256.0f) * coef);
    }
    __syncthreads();

    const float coef2 = s_sval[ll];

    // ---- softmax-weighted sum (max-free: |logit| bounded ~1.2) ----
    float se = 0.f, seh = 0.f;
#pragma unroll
    for (int i = 0; i < 16; i++) {
        float e = __expf(h[i] * coef2);
        se  += e;
        seh += e * h[i];
    }
    s_red[tid]  = se;
    s_red2[tid] = seh;
    __syncthreads();
    if (tid < 16) {
        float te = 0.f, teh = 0.f;
#pragma unroll
        for (int j = 0; j < 16; j++) {
            te  += s_red[tid + 16 * j];
            teh += s_red2[tid + 16 * j];
        }
        s_pooled[tid] = teh / te;
    }

    // ---- wait for u publication (normally already satisfied), stage u ----
    if (tid == 0) {
        while (atomicAdd(&g_prep_done, 0) < PREP_BLOCKS) { }
        __threadfence();
    }
    __syncthreads();
    s_u[tid]       = g_u[tid];
    s_u[tid + 256] = g_u[tid + 256];
    __syncthreads();

    // ---- epilogue: out[b,d,l] = pooled[l] * u[d], float4 streaming stores ----
    const int lq = tid & 3;
    const int d0 = tid >> 2;
    const float4 pv = reinterpret_cast<const float4*>(s_pooled)[lq];
    float4* out4 = reinterpret_cast<float4*>(out + (size_t)b * D_ * L_ + l_base) + lq;
#pragma unroll
    for (int k = 0; k < 8; k++) {
        int d = d0 + 64 * k;
        float ud = s_u[d];
        __stcs(&out4[(size_t)d * (L_ / 4)],
               make_float4(pv.x * ud, pv.y * ud, pv.z * ud, pv.w * ud));
    }

    // ---- replay-safe counter reset by the last finishing block ----
    if (tid == 0) {
        int n = atomicAdd(&g_main_done, 1);
        if (n == GRID_MAIN - 1) {
            g_main_done = 0;
            g_prep_done = 0;
            __threadfence();
        }
    }
}

extern "C" void kernel_launch(void* const* d_in, const int* in_sizes, int n_in,
                              void* d_out, int out_size) {
    const float* h_v   = (const float*)d_in[0];  // [B, C, L]
    const float* wq    = (const float*)d_in[1];  // [64]
    const float* wk    = (const float*)d_in[2];  // [64]
    const float* wv    = (const float*)d_in[3];  // [64]
    const float* w_out = (const float*)d_in[4];  // [512, 64]
    float* out = (float*)d_out;                  // [B, 512, L]

    fused_kernel<<<GRID_MAIN, 256>>>(h_v, wq, wk, wv, w_out, out);
}

// round 13
// speedup vs baseline: 1.5154x; 1.5154x over previous
#include <cuda_runtime.h>
#include <cuda_bf16.h>
#include <cstddef>

// Problem constants (fixed shapes per reference)
constexpr int B_ = 16;
constexpr int C_ = 256;
constexpr int L_ = 8192;
constexpr int D_ = 512;   // d_inner
constexpr int A_ = 64;    // att_dim

constexpr int PREP_BLOCKS = 32;               // blocks that also compute u
constexpr int GRID_MAIN   = B_ * (L_ / 16);   // 8192

// u[d] = w_out @ wv, published by blocks 0..31; counters reset by the last
// finishing block each run (replay-deterministic).
__device__ float g_u[D_];
__device__ int   g_prep_done;
__device__ int   g_main_done;

// Single launch. Every block processes one (b, 16-l) tile in the proven R8
// structure. Blocks 0..31 first compute u (coalesced float4 over w_out),
// __threadfence (only these 32 blocks pay gpu-fence), and bump g_prep_done.
// Consumers need u only at the EPILOGUE; tid0 polls with a plain volatile
// LOAD (no RMW, no consumer-side gpu fence -> no CCTL.IVALL storms).
__global__ void __launch_bounds__(256, 6)
fused_kernel(const float* __restrict__ h_v,
             const float* __restrict__ wq,
             const float* __restrict__ wk,
             const float* __restrict__ wv,
             const float* __restrict__ w_out,
             float* __restrict__ out) {
    __shared__ float s_u[D_];
    __shared__ float s_red[256];
    __shared__ float s_red2[256];
    __shared__ float s_sval[16];
    __shared__ __align__(16) float s_pooled[16];

    const int tid = threadIdx.x;
    const int ll  = tid & 15;   // l within tile
    const int cg  = tid >> 4;   // c-group 0..15 (16 c each)

    const int bidx   = blockIdx.x;          // 8192 blocks, tile == bidx
    const int b      = bidx >> 9;
    const int l_base = (bidx & 511) << 4;

    // ---- blocks 0..31: compute and publish u ----
    if (bidx < PREP_BLOCKS) {
        const int idx = bidx * 256 + tid;   // 0..8191 float4 chunks of w_out
        const int q   = idx & 15;
        const int row = idx >> 4;
        const float4 vv = reinterpret_cast<const float4*>(wv)[q];
        const float4 r  = reinterpret_cast<const float4*>(w_out)[idx];
        float acc = r.x * vv.x + r.y * vv.y + r.z * vv.z + r.w * vv.w;
        acc += __shfl_xor_sync(0xffffffffu, acc, 8);
        acc += __shfl_xor_sync(0xffffffffu, acc, 4);
        acc += __shfl_xor_sync(0xffffffffu, acc, 2);
        acc += __shfl_xor_sync(0xffffffffu, acc, 1);
        if (q == 0) g_u[row] = acc;
        __threadfence();            // release (32 blocks only)
        __syncthreads();
        if (tid == 0) atomicAdd(&g_prep_done, 1);
    }

    // ---- per-block coef = <wq,wk>/8 (warp 0; consumers are tid<16) ----
    float coef = 0.f;
    if (tid < 32) {
        float pqk = wq[tid] * wk[tid] + wq[tid + 32] * wk[tid + 32];
#pragma unroll
        for (int m = 16; m >= 1; m >>= 1)
            pqk += __shfl_xor_sync(0xffffffffu, pqk, m);
        coef = pqk * 0.125f;  // 1/sqrt(64)
    }

    // ---- single read of h_v: 16 values per thread (imm-offset LDGs) ----
    const float* p = h_v + ((size_t)b * C_ + (size_t)cg * 16) * L_ + l_base + ll;
    float h[16];
#pragma unroll
    for (int i = 0; i < 16; i++) h[i] = __ldcs(p + (size_t)i * L_);

    // ---- mean over C ----
    float sum = 0.f;
#pragma unroll
    for (int i = 0; i < 16; i++) sum += h[i];
    s_red[tid] = sum;
    __syncthreads();
    if (tid < 16) {
        float t = 0.f;
#pragma unroll
        for (int j = 0; j < 16; j++) t += s_red[tid + 16 * j];
        s_sval[tid] = t * ((1.0f / 256.0f) * coef);
    }
    __syncthreads();

    const float coef2 = s_sval[ll];

    // ---- softmax-weighted sum (max-free: |logit| bounded ~1.2) ----
    float se = 0.f, seh = 0.f;
#pragma unroll
    for (int i = 0; i < 16; i++) {
        float e = __expf(h[i] * coef2);
        se  += e;
        seh += e * h[i];
    }
    s_red[tid]  = se;
    s_red2[tid] = seh;
    __syncthreads();
    if (tid < 16) {
        float te = 0.f, teh = 0.f;
#pragma unroll
        for (int j = 0; j < 16; j++) {
            te  += s_red[tid + 16 * j];
            teh += s_red2[tid + 16 * j];
        }
        s_pooled[tid] = teh / te;
    }

    // ---- wait for u (volatile load poll; normally already satisfied) ----
    if (tid == 0) {
        const volatile int* f = &g_prep_done;
        while (*f < PREP_BLOCKS) { }
    }
    __syncthreads();   // orders g_u loads after the poll for all threads

    // stage u (first-touch loads: L1 has no stale copy, L2 holds published data)
    s_u[tid]       = g_u[tid];
    s_u[tid + 256] = g_u[tid + 256];
    __syncthreads();

    // ---- epilogue: out[b,d,l] = pooled[l] * u[d], float4 streaming stores ----
    const int lq = tid & 3;
    const int d0 = tid >> 2;
    const float4 pv = reinterpret_cast<const float4*>(s_pooled)[lq];
    float4* out4 = reinterpret_cast<float4*>(out + (size_t)b * D_ * L_ + l_base) + lq;
#pragma unroll
    for (int k = 0; k < 8; k++) {
        int d = d0 + 64 * k;
        float ud = s_u[d];
        __stcs(&out4[(size_t)d * (L_ / 4)],
               make_float4(pv.x * ud, pv.y * ud, pv.z * ud, pv.w * ud));
    }

    // ---- replay-safe reset by the last finishing block (all polls are
    // complete before the 8192nd increment, so the reset cannot race) ----
    if (tid == 0) {
        int n = atomicAdd(&g_main_done, 1);
        if (n == GRID_MAIN - 1) {
            g_main_done = 0;
            g_prep_done = 0;
        }
    }
}

extern "C" void kernel_launch(void* const* d_in, const int* in_sizes, int n_in,
                              void* d_out, int out_size) {
    const float* h_v   = (const float*)d_in[0];  // [B, C, L]
    const float* wq    = (const float*)d_in[1];  // [64]
    const float* wk    = (const float*)d_in[2];  // [64]
    const float* wv    = (const float*)d_in[3];  // [64]
    const float* w_out = (const float*)d_in[4];  // [512, 64]
    float* out = (float*)d_out;                  // [B, 512, L]

    fused_kernel<<<GRID_MAIN, 256>>>(h_v, wq, wk, wv, w_out, out);
}

// round 14
// speedup vs baseline: 1.5221x; 1.0044x over previous
#include <cuda_runtime.h>
#include <cuda_bf16.h>
#include <cstddef>

// Problem constants (fixed shapes per reference)
constexpr int B_ = 16;
constexpr int C_ = 256;
constexpr int L_ = 8192;
constexpr int D_ = 512;   // d_inner
constexpr int A_ = 64;    // att_dim

constexpr int PREP_BLOCKS = 32;               // blocks that also compute u
constexpr int GRID_MAIN   = B_ * (L_ / 16);   // 8192

// u[d] = w_out @ wv, published by blocks 0..31; counters reset by the last
// finishing block each run (replay-deterministic).
__device__ float g_u[D_];
__device__ int   g_prep_done;
__device__ int   g_main_done;

// Single launch, R8 tile structure (60us main, measured x4). Blocks 0..31
// compute u first (coalesced float4 over w_out) and publish. Consumers:
//   - issue the h_v LDG burst FIRST,
//   - tid0 polls g_prep_done while those loads are in flight,
//   - the existing first reduction barrier is the acquire point,
//   - u staging LDGs issue right after it, hidden under exp + 2nd reduction.
// => sync adds ~0 cycles to the per-block critical path (vs ~1000 in R13).
__global__ void __launch_bounds__(256, 6)
fused_kernel(const float* __restrict__ h_v,
             const float* __restrict__ wq,
             const float* __restrict__ wk,
             const float* __restrict__ wv,
             const float* __restrict__ w_out,
             float* __restrict__ out) {
    __shared__ float s_u[D_];
    __shared__ float s_red[256];
    __shared__ float s_red2[256];
    __shared__ float s_sval[16];
    __shared__ __align__(16) float s_pooled[16];

    const int tid = threadIdx.x;
    const int ll  = tid & 15;   // l within tile
    const int cg  = tid >> 4;   // c-group 0..15 (16 c each)

    const int bidx   = blockIdx.x;          // 8192 blocks, tile == bidx
    const int b      = bidx >> 9;
    const int l_base = (bidx & 511) << 4;

    // ---- blocks 0..31: compute and publish u before anything else ----
    if (bidx < PREP_BLOCKS) {
        const int idx = bidx * 256 + tid;   // 0..8191 float4 chunks of w_out
        const int q   = idx & 15;
        const int row = idx >> 4;
        const float4 vv = reinterpret_cast<const float4*>(wv)[q];
        const float4 r  = reinterpret_cast<const float4*>(w_out)[idx];
        float acc = r.x * vv.x + r.y * vv.y + r.z * vv.z + r.w * vv.w;
        acc += __shfl_xor_sync(0xffffffffu, acc, 8);
        acc += __shfl_xor_sync(0xffffffffu, acc, 4);
        acc += __shfl_xor_sync(0xffffffffu, acc, 2);
        acc += __shfl_xor_sync(0xffffffffu, acc, 1);
        if (q == 0) g_u[row] = acc;
        __threadfence();            // release (32 blocks only)
        __syncthreads();
        if (tid == 0) atomicAdd(&g_prep_done, 1);
    }

    // ---- per-block coef = <wq,wk>/8 (warp 0; consumers are tid<16) ----
    float coef = 0.f;
    if (tid < 32) {
        float pqk = wq[tid] * wk[tid] + wq[tid + 32] * wk[tid + 32];
#pragma unroll
        for (int m = 16; m >= 1; m >>= 1)
            pqk += __shfl_xor_sync(0xffffffffu, pqk, m);
        coef = pqk * 0.125f;  // 1/sqrt(64)
    }

    // ---- single read of h_v: 16 values per thread (imm-offset LDG burst) ----
    const float* p = h_v + ((size_t)b * C_ + (size_t)cg * 16) * L_ + l_base + ll;
    float h[16];
#pragma unroll
    for (int i = 0; i < 16; i++) h[i] = __ldcs(p + (size_t)i * L_);

    // ---- mean partial (consumes h -> waits on loads) ----
    float sum = 0.f;
#pragma unroll
    for (int i = 0; i < 16; i++) sum += h[i];
    s_red[tid] = sum;

    // ---- poll overlapped with in-flight work; barrier below = acquire ----
    if (tid == 0) {
        const volatile int* f = &g_prep_done;
        while (*f < PREP_BLOCKS) __nanosleep(64);
    }
    __syncthreads();

    // stage u now; LDG latency hides under exp phase + 2nd reduction.
    s_u[tid]       = g_u[tid];
    s_u[tid + 256] = g_u[tid + 256];

    if (tid < 16) {
        float t = 0.f;
#pragma unroll
        for (int j = 0; j < 16; j++) t += s_red[tid + 16 * j];
        s_sval[tid] = t * ((1.0f / 256.0f) * coef);
    }
    __syncthreads();

    const float coef2 = s_sval[ll];

    // ---- softmax-weighted sum (max-free: |logit| bounded ~1.2) ----
    float se = 0.f, seh = 0.f;
#pragma unroll
    for (int i = 0; i < 16; i++) {
        float e = __expf(h[i] * coef2);
        se  += e;
        seh += e * h[i];
    }
    s_red[tid]  = se;
    s_red2[tid] = seh;
    __syncthreads();
    if (tid < 16) {
        float te = 0.f, teh = 0.f;
#pragma unroll
        for (int j = 0; j < 16; j++) {
            te  += s_red[tid + 16 * j];
            teh += s_red2[tid + 16 * j];
        }
        s_pooled[tid] = teh / te;
    }
    __syncthreads();   // also orders s_u stores for the epilogue reads

    // ---- epilogue: out[b,d,l] = pooled[l] * u[d], float4 streaming stores ----
    const int lq = tid & 3;
    const int d0 = tid >> 2;
    const float4 pv = reinterpret_cast<const float4*>(s_pooled)[lq];
    float4* out4 = reinterpret_cast<float4*>(out + (size_t)b * D_ * L_ + l_base) + lq;
#pragma unroll
    for (int k = 0; k < 8; k++) {
        int d = d0 + 64 * k;
        float ud = s_u[d];
        __stcs(&out4[(size_t)d * (L_ / 4)],
               make_float4(pv.x * ud, pv.y * ud, pv.z * ud, pv.w * ud));
    }

    // ---- replay-safe reset by the last finishing block (every block has
    // passed its poll before the 8192nd increment can happen) ----
    if (tid == 0) {
        int n = atomicAdd(&g_main_done, 1);
        if (n == GRID_MAIN - 1) {
            g_main_done = 0;
            g_prep_done = 0;
        }
    }
}

extern "C" void kernel_launch(void* const* d_in, const int* in_sizes, int n_in,
                              void* d_out, int out_size) {
    const float* h_v   = (const float*)d_in[0];  // [B, C, L]
    const float* wq    = (const float*)d_in[1];  // [64]
    const float* wk    = (const float*)d_in[2];  // [64]
    const float* wv    = (const float*)d_in[3];  // [64]
    const float* w_out = (const float*)d_in[4];  // [512, 64]
    float* out = (float*)d_out;                  // [B, 512, L]

    fused_kernel<<<GRID_MAIN, 256>>>(h_v, wq, wk, wv, w_out, out);
}